// round 10
// baseline (speedup 1.0000x reference)
#include <cuda_runtime.h>
#include <cuda_fp16.h>
#include <cstdint>

#define SEQ 384
#define CIN 512
#define HW  64
#define NH  8
#define HD  64
#define K9  (CIN * 9)        // 4608
#define BP  512              // NH * HW batch-pairs
#define NROWS (SEQ * HW)     // 24576 GEMM rows
#define SS2 (SEQ * SEQ)      // 147456

// Scratch (device globals; no runtime allocation)
__device__ uint32_t g_feats_hl[(size_t)4 * BP * SEQ * HD];  // [e][bp][n][dd] packed(hi,lo)
__device__ uint32_t g_vT[(size_t)BP * HD * SEQ];            // [bp][dd][n]   packed(hi,lo)
__device__ uint32_t g_attn[(size_t)BP * SS2];               // blended attn, packed(hi,lo)
__device__ uint32_t g_c2_hl[(size_t)SEQ * CIN * HW];        // conv2 input, packed(hi,lo)
__device__ __half   g_Ah[(size_t)NROWS * K9];               // im2col hi plane (k' = r*512+ci)
__device__ __half   g_Al[(size_t)NROWS * K9];               // im2col lo plane
__device__ __half   g_wh_in[(size_t)2560 * K9];             // weights hi, k'-order
__device__ __half   g_wl_in[(size_t)2560 * K9];
__device__ __half   g_wh_out[(size_t)512 * K9];
__device__ __half   g_wl_out[(size_t)512 * K9];

// ---------------------------------------------------------------------------
// helpers
// ---------------------------------------------------------------------------
__device__ __forceinline__ uint32_t split_h2(float x)
{
    __half hi = __float2half_rn(x);
    __half lo = __float2half_rn(x - __half2float(hi));
    return (uint32_t)__half_as_ushort(hi) | ((uint32_t)__half_as_ushort(lo) << 16);
}
__device__ __forceinline__ float unsplit_h2(uint32_t p)
{
    return __half2float(__ushort_as_half((unsigned short)(p & 0xFFFF)))
         + __half2float(__ushort_as_half((unsigned short)(p >> 16)));
}

__device__ __forceinline__ void mma_f16(float c[4], const uint32_t a[4],
                                        uint32_t b0, uint32_t b1)
{
    asm volatile(
        "mma.sync.aligned.m16n8k16.row.col.f32.f16.f16.f32 "
        "{%0,%1,%2,%3}, {%4,%5,%6,%7}, {%8,%9}, {%0,%1,%2,%3};"
        : "+f"(c[0]), "+f"(c[1]), "+f"(c[2]), "+f"(c[3])
        : "r"(a[0]), "r"(a[1]), "r"(a[2]), "r"(a[3]), "r"(b0), "r"(b1));
}
__device__ __forceinline__ void ldsm4(uint32_t& r0, uint32_t& r1, uint32_t& r2,
                                      uint32_t& r3, uint32_t addr)
{
    asm volatile("ldmatrix.sync.aligned.m8n8.x4.shared.b16 {%0,%1,%2,%3}, [%4];"
                 : "=r"(r0), "=r"(r1), "=r"(r2), "=r"(r3) : "r"(addr));
}
__device__ __forceinline__ void cpa16(uint32_t dst, const void* src)
{
    asm volatile("cp.async.cg.shared.global [%0], [%1], 16;" :: "r"(dst), "l"(src));
}

// ---------------------------------------------------------------------------
// Weight split + permute to k' = r*512 + ci order
// ---------------------------------------------------------------------------
__global__ void split_w_kernel(const float* __restrict__ w,
                               __half* __restrict__ wh, __half* __restrict__ wl, int n)
{
    int i = blockIdx.x * 256 + threadIdx.x;
    if (i >= n) return;
    int co = i / K9;
    int kn = i - co * K9;
    int r = kn >> 9, ci = kn & 511;
    float x = w[(size_t)co * K9 + ci * 9 + r];
    __half hi = __float2half_rn(x);
    wh[i] = hi;
    wl[i] = __float2half_rn(x - __half2float(hi));
}

// ---------------------------------------------------------------------------
// im2col expansion into hi/lo fp16 planes, k' = r*512 + ci.
// ---------------------------------------------------------------------------
template <bool PACKED>
__global__ __launch_bounds__(256) void im2col_kernel(const float* __restrict__ srcF)
{
    __shared__ ushort th[64][72];
    __shared__ ushort tl[64][72];
    const int n   = blockIdx.x;
    const int ci0 = blockIdx.y * 64;
    const int t   = threadIdx.x;

    {
        int sp4 = (t & 15) * 4;
        int ciL = t >> 4;
        #pragma unroll
        for (int pass = 0; pass < 4; pass++) {
            int ci = pass * 16 + ciL;
            if (PACKED) {
                uint4 w = *(const uint4*)(g_c2_hl + ((size_t)n * CIN + ci0 + ci) * 64 + sp4);
                uint32_t ws[4] = {w.x, w.y, w.z, w.w};
                #pragma unroll
                for (int j = 0; j < 4; j++) {
                    th[sp4 + j][ci] = (ushort)(ws[j] & 0xFFFF);
                    tl[sp4 + j][ci] = (ushort)(ws[j] >> 16);
                }
            } else {
                float4 v = *(const float4*)(srcF + ((size_t)n * CIN + ci0 + ci) * 64 + sp4);
                float vs[4] = {v.x, v.y, v.z, v.w};
                #pragma unroll
                for (int j = 0; j < 4; j++) {
                    __half hi = __float2half_rn(vs[j]);
                    __half lo = __float2half_rn(vs[j] - __half2float(hi));
                    th[sp4 + j][ci] = __half_as_ushort(hi);
                    tl[sp4 + j][ci] = __half_as_ushort(lo);
                }
            }
        }
    }
    __syncthreads();

    const int ciQ = t & 15;
    const int rg  = t >> 4;
    #pragma unroll
    for (int si = 0; si < 4; si++) {
        int sp = si * 16 + rg;
        int yy = sp >> 3, xx = sp & 7;
        size_t obase = (size_t)(n * 64 + sp) * K9 + ci0 + ciQ * 4;
        #pragma unroll
        for (int r = 0; r < 9; r++) {
            int y = yy + r / 3 - 1, x = xx + r % 3 - 1;
            uint2 vh = make_uint2(0, 0), vl = make_uint2(0, 0);
            if ((unsigned)y < 8u && (unsigned)x < 8u) {
                int spp = y * 8 + x;
                vh = *(const uint2*)&th[spp][ciQ * 4];
                vl = *(const uint2*)&tl[spp][ciQ * 4];
            }
            *(uint2*)&g_Ah[obase + (size_t)r * 512] = vh;
            *(uint2*)&g_Al[obase + (size_t)r * 512] = vl;
        }
    }
}

// ---------------------------------------------------------------------------
// fp16x3 GEMM conv, M=256 x N=128 x BK=32, 512 threads, 3-stage cp.async ring.
// Stage layout (bytes from stage base): Ah 0 (256x20w), Al 20480,
// Bh 40960 (128x20w), Bl 51200. Stage stride 61440; 3 stages = 180KB.
// 16 warps: rbase=(wid>>1)*32 (8 m-groups), cbase=(wid&1)*64 -> warp tile
// 32x64, identical per-warp code to the validated R7 kernel.
// ---------------------------------------------------------------------------
#define LDK2 20
#define STG_B 61440
#define SMEM_BYTES (3 * STG_B)   // 184320

__device__ __forceinline__ void conv_fill(uint32_t base, int row0, int co0, int k0,
                                          int tid, const __half* gwh, const __half* gwl)
{
    // A planes: 2048 cpa16 (256 rows x 4 q x 2 planes)
    #pragma unroll
    for (int i = 0; i < 4; i++) {
        int c = i * 512 + tid;             // 0..2047
        int plane = c >> 10;               // 0=Ah, 1=Al
        int idx = c & 1023;
        int row = idx >> 2, q = idx & 3;
        uint32_t dst = base + plane * 20480u + (uint32_t)((row * LDK2 + q * 4) * 4);
        size_t src = (size_t)(row0 + row) * K9 + k0 + q * 8;
        cpa16(dst, (plane ? g_Al : g_Ah) + src);
    }
    // B planes: 1024 cpa16 (128 rows x 4 q x 2 planes)
    #pragma unroll
    for (int i = 0; i < 2; i++) {
        int c = i * 512 + tid;             // 0..1023
        int plane = c >> 9;
        int idx = c & 511;
        int row = idx >> 2, q = idx & 3;
        uint32_t dst = base + 40960u + plane * 10240u + (uint32_t)((row * LDK2 + q * 4) * 4);
        size_t src = (size_t)(co0 + row) * K9 + k0 + q * 8;
        cpa16(dst, (plane ? gwl : gwh) + src);
    }
    asm volatile("cp.async.commit_group;" ::: "memory");
}

template <int CO, bool FIRST>
__global__ void __launch_bounds__(512, 1)
conv_f16_kernel(const __half* __restrict__ gwh,
                const __half* __restrict__ gwl,
                const float* __restrict__ bias,
                float* __restrict__ out)
{
    extern __shared__ uint32_t sm[];
    const uint32_t smb = (uint32_t)__cvta_generic_to_shared(sm);

    const int row0 = blockIdx.y * 256;
    const int co0  = blockIdx.x * 128;
    const int tid  = threadIdx.x;
    const int lane = tid & 31, wid = tid >> 5;
    const int rbase = (wid >> 1) * 32;     // 0..224
    const int cbase = (wid & 1) * 64;
    const int lg = lane >> 2, lt = lane & 3;

    const int aRow = lane & 15, aCol = (lane >> 4) * 4;
    const int bRow = ((lane >> 4) & 1) * 8 + (lane & 7);
    const int bCol = ((lane >> 3) & 1) * 4;

    float acc[2][8][4] = {};

    const int NITER = K9 / 32;   // 144
    conv_fill(smb,         row0, co0, 0,  tid, gwh, gwl);
    conv_fill(smb + STG_B, row0, co0, 32, tid, gwh, gwl);

    for (int it = 0; it < NITER; it++) {
        asm volatile("cp.async.wait_group 1;" ::: "memory");   // fill(it) complete
        __syncthreads();   // all warps past compute(it-1) -> buffer (it+2)%3 free
        if (it + 2 < NITER)
            conv_fill(smb + ((it + 2) % 3) * STG_B, row0, co0, (it + 2) * 32,
                      tid, gwh, gwl);

        const uint32_t base = smb + (it % 3) * STG_B;
        #pragma unroll
        for (int k16 = 0; k16 < 2; k16++) {
            const uint32_t ko = k16 * 8;
            uint32_t ah[2][4], al[2][4];
            #pragma unroll
            for (int mt = 0; mt < 2; mt++) {
                uint32_t aw = base + ((rbase + mt * 16 + aRow) * LDK2 + aCol + ko) * 4;
                ldsm4(ah[mt][0], ah[mt][1], ah[mt][2], ah[mt][3], aw);
                ldsm4(al[mt][0], al[mt][1], al[mt][2], al[mt][3], aw + 20480);
            }
            #pragma unroll
            for (int pr = 0; pr < 4; pr++) {
                uint32_t bw = base + 40960 +
                              ((cbase + pr * 16 + bRow) * LDK2 + bCol + ko) * 4;
                uint32_t bh0, bh1, bh2, bh3, bl0, bl1, bl2, bl3;
                ldsm4(bh0, bh1, bh2, bh3, bw);
                ldsm4(bl0, bl1, bl2, bl3, bw + 10240);
                #pragma unroll
                for (int mt = 0; mt < 2; mt++) {
                    mma_f16(acc[mt][2 * pr],     ah[mt], bh0, bh1);
                    mma_f16(acc[mt][2 * pr],     ah[mt], bl0, bl1);
                    mma_f16(acc[mt][2 * pr],     al[mt], bh0, bh1);
                    mma_f16(acc[mt][2 * pr + 1], ah[mt], bh2, bh3);
                    mma_f16(acc[mt][2 * pr + 1], ah[mt], bl2, bl3);
                    mma_f16(acc[mt][2 * pr + 1], al[mt], bh2, bh3);
                }
            }
        }
    }

    // ---- epilogue ----
    #pragma unroll
    for (int mt = 0; mt < 2; mt++) {
        #pragma unroll
        for (int nt = 0; nt < 8; nt++) {
            #pragma unroll
            for (int cp = 0; cp < 4; cp++) {
                int row = row0 + rbase + mt * 16 + lg + ((cp >= 2) ? 8 : 0);
                int col = cbase + nt * 8 + lt * 2 + (cp & 1);
                int co  = co0 + col;
                float v = acc[mt][nt][cp] + bias[co];
                int n = row >> 6, sp = row & 63;
                if (FIRST) {
                    int e  = co >> 9;
                    int dd = (co >> 3) & 63;
                    int hh = co & 7;
                    int bpi = hh * 64 + sp;
                    uint32_t pv = split_h2(v);
                    if (e < 4)
                        g_feats_hl[(((size_t)e * BP + bpi) * SEQ + n) * HD + dd] = pv;
                    else
                        g_vT[((size_t)bpi * HD + dd) * SEQ + n] = pv;
                } else {
                    out[((size_t)n * CO + co) * 64 + sp] = v;
                }
            }
        }
    }
}

// ---------------------------------------------------------------------------
// Fused QK + dual softmax + agent blend (unchanged from R9).
// ---------------------------------------------------------------------------
#define FA_SMEM 136192
#define SST 388
#define QH_OFF 24832
#define QL_OFF 27136
#define KH_OFF 29440
#define KL_OFF 31744

__global__ void __launch_bounds__(256, 1)
fused_qk_softmax_kernel(const float* __restrict__ am, const int* __restrict__ agent)
{
    extern __shared__ uint32_t sm[];
    float* Sf = (float*)sm;
    const uint32_t smb = (uint32_t)__cvta_generic_to_shared(sm);

    const int m0 = blockIdx.x * 64;
    const int bp = blockIdx.y;
    const int head = bp >> 6;
    const int tid = threadIdx.x, lane = tid & 31, wid = tid >> 5;
    const int wq = (wid & 3) * 16;
    const int wc = (wid >> 2) * 32;
    const int lg = lane >> 2, lt = lane & 3;
    const int aRow = lane & 15, aCol = (lane >> 4) * 4;
    const int bRow = ((lane >> 4) & 1) * 8 + (lane & 7);
    const int bCol = ((lane >> 3) & 1) * 4;

    for (int v = 0; v < 2; v++) {
        const uint32_t* Q = g_feats_hl + (((size_t)(2 + v) * BP + bp) * SEQ + m0) * HD;
        #pragma unroll
        for (int i = 0; i < 4; i++) {
            int lin = i * 256 + tid;
            int row = lin >> 4, q4 = lin & 15;
            uint4 w = *(const uint4*)(Q + (size_t)row * HD + q4 * 4);
            int o = row * 36 + q4 * 2;
            *(uint2*)&sm[QH_OFF + o] = make_uint2(__byte_perm(w.x, w.y, 0x5410),
                                                  __byte_perm(w.z, w.w, 0x5410));
            *(uint2*)&sm[QL_OFF + o] = make_uint2(__byte_perm(w.x, w.y, 0x7632),
                                                  __byte_perm(w.z, w.w, 0x7632));
        }

        const uint32_t* Kv = g_feats_hl + ((size_t)v * BP + bp) * SEQ * HD;
        for (int kc = 0; kc < 6; kc++) {
            __syncthreads();
            #pragma unroll
            for (int i = 0; i < 4; i++) {
                int lin = i * 256 + tid;
                int row = lin >> 4, q4 = lin & 15;
                uint4 w = *(const uint4*)(Kv + (size_t)(kc * 64 + row) * HD + q4 * 4);
                int o = row * 36 + q4 * 2;
                *(uint2*)&sm[KH_OFF + o] = make_uint2(__byte_perm(w.x, w.y, 0x5410),
                                                      __byte_perm(w.z, w.w, 0x5410));
                *(uint2*)&sm[KL_OFF + o] = make_uint2(__byte_perm(w.x, w.y, 0x7632),
                                                      __byte_perm(w.z, w.w, 0x7632));
            }
            __syncthreads();

            float acc[4][4] = {};
            #pragma unroll
            for (int k16 = 0; k16 < 4; k16++) {
                const int ko = k16 * 8;
                uint32_t ah[4], al[4];
                uint32_t aw = smb + (QH_OFF + (wq + aRow) * 36 + aCol + ko) * 4;
                ldsm4(ah[0], ah[1], ah[2], ah[3], aw);
                ldsm4(al[0], al[1], al[2], al[3], aw + (QL_OFF - QH_OFF) * 4);
                #pragma unroll
                for (int pr = 0; pr < 2; pr++) {
                    uint32_t bw = smb + (KH_OFF + (wc + pr * 16 + bRow) * 36 + bCol + ko) * 4;
                    uint32_t bh0, bh1, bh2, bh3, bl0, bl1, bl2, bl3;
                    ldsm4(bh0, bh1, bh2, bh3, bw);
                    ldsm4(bl0, bl1, bl2, bl3, bw + (KL_OFF - KH_OFF) * 4);
                    mma_f16(acc[pr * 2],     ah, bh0, bh1);
                    mma_f16(acc[pr * 2],     ah, bl0, bl1);
                    mma_f16(acc[pr * 2],     al, bh0, bh1);
                    mma_f16(acc[pr * 2 + 1], ah, bh2, bh3);
                    mma_f16(acc[pr * 2 + 1], ah, bl2, bl3);
                    mma_f16(acc[pr * 2 + 1], al, bh2, bh3);
                }
            }
            #pragma unroll
            for (int nt = 0; nt < 4; nt++) {
                #pragma unroll
                for (int cp = 0; cp < 4; cp++) {
                    int q   = wq + lg + ((cp >= 2) ? 8 : 0);
                    int col = kc * 64 + wc + nt * 8 + lt * 2 + (cp & 1);
                    Sf[q * SST + col] = acc[nt][cp];
                }
            }
        }
        __syncthreads();

        #pragma unroll
        for (int r8 = 0; r8 < 8; r8++) {
            int row = wid * 8 + r8;
            int gq  = m0 + row;
            const float* amr = am + ((size_t)head * SEQ + gq) * SEQ;
            float e[12];
            float M = -1e30f;
            #pragma unroll
            for (int j = 0; j < 12; j++) {
                float s = Sf[row * SST + lane + 32 * j] * 0.125f + amr[lane + 32 * j];
                e[j] = s;
                M = fmaxf(M, s);
            }
            #pragma unroll
            for (int o = 16; o; o >>= 1) M = fmaxf(M, __shfl_xor_sync(~0u, M, o));
            float Z = 0.f;
            #pragma unroll
            for (int j = 0; j < 12; j++) { e[j] = __expf(e[j] - M); Z += e[j]; }
            #pragma unroll
            for (int o = 16; o; o >>= 1) Z += __shfl_xor_sync(~0u, Z, o);
            float rz = 1.f / Z;

            uint32_t* arow = g_attn + ((size_t)bp * SEQ + gq) * SEQ;
            if (v == 0) {
                #pragma unroll
                for (int j = 0; j < 12; j++)
                    arow[lane + 32 * j] = split_h2(e[j] * rz);
            } else {
                const int* mr = agent + ((size_t)head * SEQ + gq) * SEQ;
                #pragma unroll
                for (int j = 0; j < 12; j++) {
                    float a_same = unsplit_h2(arow[lane + 32 * j]);
                    float m = (float)mr[lane + 32 * j];
                    arow[lane + 32 * j] =
                        split_h2(m * a_same + (1.f - m) * e[j] * rz);
                }
            }
        }
    }
}

// ---------------------------------------------------------------------------
// AV on fp16x3 MMA (unchanged from R9).
// ---------------------------------------------------------------------------
#define AV_SMEM (13824 * 4)

__global__ void __launch_bounds__(256, 2)
av_mma_kernel()
{
    extern __shared__ uint32_t sm[];
    const uint32_t smb = (uint32_t)__cvta_generic_to_shared(sm);

    const int bp = blockIdx.y, m0 = blockIdx.x * 128;
    const int hh = bp >> 6, p = bp & 63;
    const int tid = threadIdx.x, lane = tid & 31, wid = tid >> 5;
    const int rbase = (wid & 3) * 32, cbase = (wid >> 2) * 32;
    const int lg = lane >> 2, lt = lane & 3;
    const int aRow = lane & 15, aCol = (lane >> 4) * 4;
    const int bRow = ((lane >> 4) & 1) * 8 + (lane & 7);
    const int bCol = ((lane >> 3) & 1) * 4;

    const uint32_t* A = g_attn + (size_t)bp * SS2 + (size_t)m0 * SEQ;
    const uint32_t* V = g_vT + (size_t)bp * HD * SEQ;

    float acc[2][4][4] = {};

    for (int ks = 0; ks < 6; ks++) {
        const int k0 = ks * 64;
        __syncthreads();
        #pragma unroll
        for (int i = 0; i < 16; i++) {
            int lin = i * 256 + tid;
            int row = lin >> 5, p2 = lin & 31;
            uint2 w = *(const uint2*)(A + (size_t)row * SEQ + k0 + p2 * 2);
            sm[row * 36 + p2]        = __byte_perm(w.x, w.y, 0x5410);
            sm[4608 + row * 36 + p2] = __byte_perm(w.x, w.y, 0x7632);
        }
        #pragma unroll
        for (int i = 0; i < 8; i++) {
            int lin = i * 256 + tid;
            int row = lin >> 5, p2 = lin & 31;
            uint2 w = *(const uint2*)(V + (size_t)row * SEQ + k0 + p2 * 2);
            sm[9216 + row * 36 + p2]  = __byte_perm(w.x, w.y, 0x5410);
            sm[11520 + row * 36 + p2] = __byte_perm(w.x, w.y, 0x7632);
        }
        __syncthreads();

        #pragma unroll
        for (int k16 = 0; k16 < 4; k16++) {
            const int ko = k16 * 8;
            uint32_t ah[2][4], al[2][4];
            #pragma unroll
            for (int mt = 0; mt < 2; mt++) {
                uint32_t aw = smb + ((rbase + mt * 16 + aRow) * 36 + aCol + ko) * 4;
                ldsm4(ah[mt][0], ah[mt][1], ah[mt][2], ah[mt][3], aw);
                ldsm4(al[mt][0], al[mt][1], al[mt][2], al[mt][3], aw + 18432);
            }
            #pragma unroll
            for (int pr = 0; pr < 2; pr++) {
                uint32_t bw = smb + 36864 + ((cbase + pr * 16 + bRow) * 36 + bCol + ko) * 4;
                uint32_t bh0, bh1, bh2, bh3, bl0, bl1, bl2, bl3;
                ldsm4(bh0, bh1, bh2, bh3, bw);
                ldsm4(bl0, bl1, bl2, bl3, bw + 9216);
                #pragma unroll
                for (int mt = 0; mt < 2; mt++) {
                    mma_f16(acc[mt][2 * pr],     ah[mt], bh0, bh1);
                    mma_f16(acc[mt][2 * pr],     ah[mt], bl0, bl1);
                    mma_f16(acc[mt][2 * pr],     al[mt], bh0, bh1);
                    mma_f16(acc[mt][2 * pr + 1], ah[mt], bh2, bh3);
                    mma_f16(acc[mt][2 * pr + 1], ah[mt], bl2, bl3);
                    mma_f16(acc[mt][2 * pr + 1], al[mt], bh2, bh3);
                }
            }
        }
    }

    #pragma unroll
    for (int mt = 0; mt < 2; mt++) {
        #pragma unroll
        for (int nt = 0; nt < 4; nt++) {
            #pragma unroll
            for (int cp = 0; cp < 4; cp++) {
                int q  = m0 + rbase + mt * 16 + lg + ((cp >= 2) ? 8 : 0);
                int dd = cbase + nt * 8 + lt * 2 + (cp & 1);
                g_c2_hl[((size_t)q * CIN + (dd * 8 + hh)) * 64 + p] =
                    split_h2(acc[mt][nt][cp]);
            }
        }
    }
}

// ---------------------------------------------------------------------------
extern "C" void kernel_launch(void* const* d_in, const int* in_sizes, int n_in,
                              void* d_out, int out_size)
{
    const float* inp       = (const float*)d_in[0];
    const float* attn_mask = (const float*)d_in[1];
    const int*   agent     = (const int*)  d_in[2];
    const float* w_in      = (const float*)d_in[3];
    const float* b_in      = (const float*)d_in[4];
    const float* w_out     = (const float*)d_in[5];
    const float* b_out     = (const float*)d_in[6];
    float*       out       = (float*)d_out;

    __half *wh_in, *wl_in, *wh_out, *wl_out;
    cudaGetSymbolAddress((void**)&wh_in,  g_wh_in);
    cudaGetSymbolAddress((void**)&wl_in,  g_wl_in);
    cudaGetSymbolAddress((void**)&wh_out, g_wh_out);
    cudaGetSymbolAddress((void**)&wl_out, g_wl_out);

    cudaFuncSetAttribute(conv_f16_kernel<2560, true>,
                         cudaFuncAttributeMaxDynamicSharedMemorySize, SMEM_BYTES);
    cudaFuncSetAttribute(conv_f16_kernel<512, false>,
                         cudaFuncAttributeMaxDynamicSharedMemorySize, SMEM_BYTES);
    cudaFuncSetAttribute(fused_qk_softmax_kernel,
                         cudaFuncAttributeMaxDynamicSharedMemorySize, FA_SMEM);
    cudaFuncSetAttribute(av_mma_kernel,
                         cudaFuncAttributeMaxDynamicSharedMemorySize, AV_SMEM);

    const int n_win  = 2560 * K9;
    const int n_wout = 512 * K9;
    split_w_kernel<<<(n_win + 255) / 256, 256>>>(w_in, wh_in, wl_in, n_win);
    split_w_kernel<<<(n_wout + 255) / 256, 256>>>(w_out, wh_out, wl_out, n_wout);

    // im2col expansion of raw input
    im2col_kernel<false><<<dim3(SEQ, 8), 256>>>(inp);

    // conv_in GEMM: M = 24576 (96 blocks of 256), N = 2560 (20 tiles)
    conv_f16_kernel<2560, true><<<dim3(20, 96), 512, SMEM_BYTES>>>(wh_in, wl_in, b_in, nullptr);

    // fused scores + dual softmax + agent blend -> packed attn
    fused_qk_softmax_kernel<<<dim3(6, BP), 256, FA_SMEM>>>(attn_mask, agent);

    // attn @ V on tensor cores -> packed conv2 input
    av_mma_kernel<<<dim3(3, BP), 256, AV_SMEM>>>();

    // im2col expansion of attention output (packed source)
    im2col_kernel<true><<<dim3(SEQ, 8), 256>>>(nullptr);

    // conv_out GEMM: N = 512 (4 tiles)
    conv_f16_kernel<512, false><<<dim3(4, 96), 512, SMEM_BYTES>>>(wh_out, wl_out, b_out, out);
}

// round 11
// speedup vs baseline: 1.0707x; 1.0707x over previous
#include <cuda_runtime.h>
#include <cuda_fp16.h>
#include <cstdint>

#define SEQ 384
#define CIN 512
#define HW  64
#define NH  8
#define HD  64
#define K9  (CIN * 9)        // 4608
#define BP  512              // NH * HW batch-pairs
#define NROWS (SEQ * HW)     // 24576 GEMM rows
#define SS2 (SEQ * SEQ)      // 147456

// Scratch (device globals; no runtime allocation)
__device__ uint32_t g_feats_hl[(size_t)4 * BP * SEQ * HD];  // [e][bp][n][dd] packed(hi,lo)
__device__ uint32_t g_vT[(size_t)BP * HD * SEQ];            // [bp][dd][n]   packed(hi,lo)
__device__ uint32_t g_attn[(size_t)BP * SS2];               // blended attn, packed(hi,lo)
__device__ uint32_t g_c2_hl[(size_t)SEQ * CIN * HW];        // conv2 input, packed(hi,lo)
__device__ __half   g_Ah[(size_t)NROWS * K9];               // im2col hi plane (k' = r*512+ci)
__device__ __half   g_Al[(size_t)NROWS * K9];               // im2col lo plane
__device__ __half   g_wh_in[(size_t)2560 * K9];             // weights hi, k'-order
__device__ __half   g_wl_in[(size_t)2560 * K9];
__device__ __half   g_wh_out[(size_t)512 * K9];
__device__ __half   g_wl_out[(size_t)512 * K9];

// ---------------------------------------------------------------------------
// helpers
// ---------------------------------------------------------------------------
__device__ __forceinline__ uint32_t split_h2(float x)
{
    __half hi = __float2half_rn(x);
    __half lo = __float2half_rn(x - __half2float(hi));
    return (uint32_t)__half_as_ushort(hi) | ((uint32_t)__half_as_ushort(lo) << 16);
}
__device__ __forceinline__ float unsplit_h2(uint32_t p)
{
    return __half2float(__ushort_as_half((unsigned short)(p & 0xFFFF)))
         + __half2float(__ushort_as_half((unsigned short)(p >> 16)));
}

__device__ __forceinline__ void mma_f16(float c[4], const uint32_t a[4],
                                        uint32_t b0, uint32_t b1)
{
    asm volatile(
        "mma.sync.aligned.m16n8k16.row.col.f32.f16.f16.f32 "
        "{%0,%1,%2,%3}, {%4,%5,%6,%7}, {%8,%9}, {%0,%1,%2,%3};"
        : "+f"(c[0]), "+f"(c[1]), "+f"(c[2]), "+f"(c[3])
        : "r"(a[0]), "r"(a[1]), "r"(a[2]), "r"(a[3]), "r"(b0), "r"(b1));
}
__device__ __forceinline__ void ldsm4(uint32_t& r0, uint32_t& r1, uint32_t& r2,
                                      uint32_t& r3, uint32_t addr)
{
    asm volatile("ldmatrix.sync.aligned.m8n8.x4.shared.b16 {%0,%1,%2,%3}, [%4];"
                 : "=r"(r0), "=r"(r1), "=r"(r2), "=r"(r3) : "r"(addr));
}
__device__ __forceinline__ void cpa16(uint32_t dst, const void* src)
{
    asm volatile("cp.async.cg.shared.global [%0], [%1], 16;" :: "r"(dst), "l"(src));
}

// ---------------------------------------------------------------------------
// Weight split + permute to k' = r*512 + ci order
// ---------------------------------------------------------------------------
__global__ void split_w_kernel(const float* __restrict__ w,
                               __half* __restrict__ wh, __half* __restrict__ wl, int n)
{
    int i = blockIdx.x * 256 + threadIdx.x;
    if (i >= n) return;
    int co = i / K9;
    int kn = i - co * K9;
    int r = kn >> 9, ci = kn & 511;
    float x = w[(size_t)co * K9 + ci * 9 + r];
    __half hi = __float2half_rn(x);
    wh[i] = hi;
    wl[i] = __float2half_rn(x - __half2float(hi));
}

// ---------------------------------------------------------------------------
// im2col expansion into hi/lo fp16 planes, k' = r*512 + ci.
// ---------------------------------------------------------------------------
template <bool PACKED>
__global__ __launch_bounds__(256) void im2col_kernel(const float* __restrict__ srcF)
{
    __shared__ ushort th[64][72];
    __shared__ ushort tl[64][72];
    const int n   = blockIdx.x;
    const int ci0 = blockIdx.y * 64;
    const int t   = threadIdx.x;

    {
        int sp4 = (t & 15) * 4;
        int ciL = t >> 4;
        #pragma unroll
        for (int pass = 0; pass < 4; pass++) {
            int ci = pass * 16 + ciL;
            if (PACKED) {
                uint4 w = *(const uint4*)(g_c2_hl + ((size_t)n * CIN + ci0 + ci) * 64 + sp4);
                uint32_t ws[4] = {w.x, w.y, w.z, w.w};
                #pragma unroll
                for (int j = 0; j < 4; j++) {
                    th[sp4 + j][ci] = (ushort)(ws[j] & 0xFFFF);
                    tl[sp4 + j][ci] = (ushort)(ws[j] >> 16);
                }
            } else {
                float4 v = *(const float4*)(srcF + ((size_t)n * CIN + ci0 + ci) * 64 + sp4);
                float vs[4] = {v.x, v.y, v.z, v.w};
                #pragma unroll
                for (int j = 0; j < 4; j++) {
                    __half hi = __float2half_rn(vs[j]);
                    __half lo = __float2half_rn(vs[j] - __half2float(hi));
                    th[sp4 + j][ci] = __half_as_ushort(hi);
                    tl[sp4 + j][ci] = __half_as_ushort(lo);
                }
            }
        }
    }
    __syncthreads();

    const int ciQ = t & 15;
    const int rg  = t >> 4;
    #pragma unroll
    for (int si = 0; si < 4; si++) {
        int sp = si * 16 + rg;
        int yy = sp >> 3, xx = sp & 7;
        size_t obase = (size_t)(n * 64 + sp) * K9 + ci0 + ciQ * 4;
        #pragma unroll
        for (int r = 0; r < 9; r++) {
            int y = yy + r / 3 - 1, x = xx + r % 3 - 1;
            uint2 vh = make_uint2(0, 0), vl = make_uint2(0, 0);
            if ((unsigned)y < 8u && (unsigned)x < 8u) {
                int spp = y * 8 + x;
                vh = *(const uint2*)&th[spp][ciQ * 4];
                vl = *(const uint2*)&tl[spp][ciQ * 4];
            }
            *(uint2*)&g_Ah[obase + (size_t)r * 512] = vh;
            *(uint2*)&g_Al[obase + (size_t)r * 512] = vl;
        }
    }
}

// ---------------------------------------------------------------------------
// fp16x3 GEMM conv (R7/R9 structure: 128x128, 256 thr, 2-stage cp.async).
// Changes vs R9: (a) MMA block reordered by split term -> 4 independent
// accumulator chains interleaved; (b) trailing barrier removed (top-of-loop
// wait+sync already proves the refill target buffer is free).
// ---------------------------------------------------------------------------
#define LDK2 20
#define STG_BYTES (4 * 128 * LDK2 * 4)
#define SMEM_BYTES (2 * STG_BYTES)

__device__ __forceinline__ void conv_fill(uint32_t base, int row0, int co0, int k0,
                                          int tid, const __half* gwh, const __half* gwl)
{
    #pragma unroll
    for (int h = 0; h < 2; h++) {
        int c = h * 256 + tid;
        int row = c >> 2, q = c & 3;
        uint32_t doff = (uint32_t)((row * LDK2 + q * 4) * 4);
        size_t aoff = (size_t)(row0 + row) * K9 + k0 + q * 8;
        size_t boff = (size_t)(co0 + row) * K9 + k0 + q * 8;
        cpa16(base + doff,         g_Ah + aoff);
        cpa16(base + 10240 + doff, g_Al + aoff);
        cpa16(base + 20480 + doff, gwh + boff);
        cpa16(base + 30720 + doff, gwl + boff);
    }
    asm volatile("cp.async.commit_group;" ::: "memory");
}

template <int CO, bool FIRST>
__global__ void __launch_bounds__(256, 2)
conv_f16_kernel(const __half* __restrict__ gwh,
                const __half* __restrict__ gwl,
                const float* __restrict__ bias,
                float* __restrict__ out)
{
    extern __shared__ uint32_t sm[];
    const uint32_t smb = (uint32_t)__cvta_generic_to_shared(sm);

    const int row0 = blockIdx.y * 128;
    const int co0  = blockIdx.x * 128;
    const int tid  = threadIdx.x;
    const int lane = tid & 31, wid = tid >> 5;
    const int rbase = (wid >> 1) * 32;
    const int cbase = (wid & 1) * 64;
    const int lg = lane >> 2, lt = lane & 3;

    const int aRow = lane & 15, aCol = (lane >> 4) * 4;
    const int bRow = ((lane >> 4) & 1) * 8 + (lane & 7);
    const int bCol = ((lane >> 3) & 1) * 4;

    float acc[2][8][4] = {};

    conv_fill(smb, row0, co0, 0, tid, gwh, gwl);

    const int NITER = K9 / 32;
    for (int it = 0; it < NITER; it++) {
        const int s = it & 1;
        asm volatile("cp.async.wait_group 0;" ::: "memory");
        __syncthreads();   // fill(it) visible to all; all warps past compute(it-1)
        if (it + 1 < NITER)
            conv_fill(smb + (1 - s) * STG_BYTES, row0, co0, (it + 1) * 32, tid, gwh, gwl);

        const uint32_t base = smb + s * STG_BYTES;
        #pragma unroll
        for (int k16 = 0; k16 < 2; k16++) {
            const uint32_t ko = k16 * 8;
            uint32_t ah[2][4], al[2][4];
            #pragma unroll
            for (int mt = 0; mt < 2; mt++) {
                uint32_t aw = base + ((rbase + mt * 16 + aRow) * LDK2 + aCol + ko) * 4;
                ldsm4(ah[mt][0], ah[mt][1], ah[mt][2], ah[mt][3], aw);
                ldsm4(al[mt][0], al[mt][1], al[mt][2], al[mt][3], aw + 10240);
            }
            #pragma unroll
            for (int pr = 0; pr < 4; pr++) {
                uint32_t bw = base + 20480 +
                              ((cbase + pr * 16 + bRow) * LDK2 + bCol + ko) * 4;
                uint32_t bh0, bh1, bh2, bh3, bl0, bl1, bl2, bl3;
                ldsm4(bh0, bh1, bh2, bh3, bw);
                ldsm4(bl0, bl1, bl2, bl3, bw + 10240);
                // Term-major order: 4 independent accumulator chains interleaved
                // (same per-acc term sequence hh -> hl -> lh as before).
                mma_f16(acc[0][2 * pr],     ah[0], bh0, bh1);
                mma_f16(acc[1][2 * pr],     ah[1], bh0, bh1);
                mma_f16(acc[0][2 * pr + 1], ah[0], bh2, bh3);
                mma_f16(acc[1][2 * pr + 1], ah[1], bh2, bh3);
                mma_f16(acc[0][2 * pr],     ah[0], bl0, bl1);
                mma_f16(acc[1][2 * pr],     ah[1], bl0, bl1);
                mma_f16(acc[0][2 * pr + 1], ah[0], bl2, bl3);
                mma_f16(acc[1][2 * pr + 1], ah[1], bl2, bl3);
                mma_f16(acc[0][2 * pr],     al[0], bh0, bh1);
                mma_f16(acc[1][2 * pr],     al[1], bh0, bh1);
                mma_f16(acc[0][2 * pr + 1], al[0], bh2, bh3);
                mma_f16(acc[1][2 * pr + 1], al[1], bh2, bh3);
            }
        }
        // no trailing barrier
    }

    // ---- epilogue ----
    #pragma unroll
    for (int mt = 0; mt < 2; mt++) {
        #pragma unroll
        for (int nt = 0; nt < 8; nt++) {
            #pragma unroll
            for (int cp = 0; cp < 4; cp++) {
                int row = row0 + rbase + mt * 16 + lg + ((cp >= 2) ? 8 : 0);
                int col = cbase + nt * 8 + lt * 2 + (cp & 1);
                int co  = co0 + col;
                float v = acc[mt][nt][cp] + bias[co];
                int n = row >> 6, sp = row & 63;
                if (FIRST) {
                    int e  = co >> 9;
                    int dd = (co >> 3) & 63;
                    int hh = co & 7;
                    int bpi = hh * 64 + sp;
                    uint32_t pv = split_h2(v);
                    if (e < 4)
                        g_feats_hl[(((size_t)e * BP + bpi) * SEQ + n) * HD + dd] = pv;
                    else
                        g_vT[((size_t)bpi * HD + dd) * SEQ + n] = pv;
                } else {
                    out[((size_t)n * CO + co) * 64 + sp] = v;
                }
            }
        }
    }
}

// ---------------------------------------------------------------------------
// Fused QK + dual softmax + agent blend (unchanged from R9).
// ---------------------------------------------------------------------------
#define FA_SMEM 136192
#define SST 388
#define QH_OFF 24832
#define QL_OFF 27136
#define KH_OFF 29440
#define KL_OFF 31744

__global__ void __launch_bounds__(256, 1)
fused_qk_softmax_kernel(const float* __restrict__ am, const int* __restrict__ agent)
{
    extern __shared__ uint32_t sm[];
    float* Sf = (float*)sm;
    const uint32_t smb = (uint32_t)__cvta_generic_to_shared(sm);

    const int m0 = blockIdx.x * 64;
    const int bp = blockIdx.y;
    const int head = bp >> 6;
    const int tid = threadIdx.x, lane = tid & 31, wid = tid >> 5;
    const int wq = (wid & 3) * 16;
    const int wc = (wid >> 2) * 32;
    const int lg = lane >> 2, lt = lane & 3;
    const int aRow = lane & 15, aCol = (lane >> 4) * 4;
    const int bRow = ((lane >> 4) & 1) * 8 + (lane & 7);
    const int bCol = ((lane >> 3) & 1) * 4;

    for (int v = 0; v < 2; v++) {
        const uint32_t* Q = g_feats_hl + (((size_t)(2 + v) * BP + bp) * SEQ + m0) * HD;
        #pragma unroll
        for (int i = 0; i < 4; i++) {
            int lin = i * 256 + tid;
            int row = lin >> 4, q4 = lin & 15;
            uint4 w = *(const uint4*)(Q + (size_t)row * HD + q4 * 4);
            int o = row * 36 + q4 * 2;
            *(uint2*)&sm[QH_OFF + o] = make_uint2(__byte_perm(w.x, w.y, 0x5410),
                                                  __byte_perm(w.z, w.w, 0x5410));
            *(uint2*)&sm[QL_OFF + o] = make_uint2(__byte_perm(w.x, w.y, 0x7632),
                                                  __byte_perm(w.z, w.w, 0x7632));
        }

        const uint32_t* Kv = g_feats_hl + ((size_t)v * BP + bp) * SEQ * HD;
        for (int kc = 0; kc < 6; kc++) {
            __syncthreads();
            #pragma unroll
            for (int i = 0; i < 4; i++) {
                int lin = i * 256 + tid;
                int row = lin >> 4, q4 = lin & 15;
                uint4 w = *(const uint4*)(Kv + (size_t)(kc * 64 + row) * HD + q4 * 4);
                int o = row * 36 + q4 * 2;
                *(uint2*)&sm[KH_OFF + o] = make_uint2(__byte_perm(w.x, w.y, 0x5410),
                                                      __byte_perm(w.z, w.w, 0x5410));
                *(uint2*)&sm[KL_OFF + o] = make_uint2(__byte_perm(w.x, w.y, 0x7632),
                                                      __byte_perm(w.z, w.w, 0x7632));
            }
            __syncthreads();

            float acc[4][4] = {};
            #pragma unroll
            for (int k16 = 0; k16 < 4; k16++) {
                const int ko = k16 * 8;
                uint32_t ah[4], al[4];
                uint32_t aw = smb + (QH_OFF + (wq + aRow) * 36 + aCol + ko) * 4;
                ldsm4(ah[0], ah[1], ah[2], ah[3], aw);
                ldsm4(al[0], al[1], al[2], al[3], aw + (QL_OFF - QH_OFF) * 4);
                #pragma unroll
                for (int pr = 0; pr < 2; pr++) {
                    uint32_t bw = smb + (KH_OFF + (wc + pr * 16 + bRow) * 36 + bCol + ko) * 4;
                    uint32_t bh0, bh1, bh2, bh3, bl0, bl1, bl2, bl3;
                    ldsm4(bh0, bh1, bh2, bh3, bw);
                    ldsm4(bl0, bl1, bl2, bl3, bw + (KL_OFF - KH_OFF) * 4);
                    mma_f16(acc[pr * 2],     ah, bh0, bh1);
                    mma_f16(acc[pr * 2],     ah, bl0, bl1);
                    mma_f16(acc[pr * 2],     al, bh0, bh1);
                    mma_f16(acc[pr * 2 + 1], ah, bh2, bh3);
                    mma_f16(acc[pr * 2 + 1], ah, bl2, bl3);
                    mma_f16(acc[pr * 2 + 1], al, bh2, bh3);
                }
            }
            #pragma unroll
            for (int nt = 0; nt < 4; nt++) {
                #pragma unroll
                for (int cp = 0; cp < 4; cp++) {
                    int q   = wq + lg + ((cp >= 2) ? 8 : 0);
                    int col = kc * 64 + wc + nt * 8 + lt * 2 + (cp & 1);
                    Sf[q * SST + col] = acc[nt][cp];
                }
            }
        }
        __syncthreads();

        #pragma unroll
        for (int r8 = 0; r8 < 8; r8++) {
            int row = wid * 8 + r8;
            int gq  = m0 + row;
            const float* amr = am + ((size_t)head * SEQ + gq) * SEQ;
            float e[12];
            float M = -1e30f;
            #pragma unroll
            for (int j = 0; j < 12; j++) {
                float s = Sf[row * SST + lane + 32 * j] * 0.125f + amr[lane + 32 * j];
                e[j] = s;
                M = fmaxf(M, s);
            }
            #pragma unroll
            for (int o = 16; o; o >>= 1) M = fmaxf(M, __shfl_xor_sync(~0u, M, o));
            float Z = 0.f;
            #pragma unroll
            for (int j = 0; j < 12; j++) { e[j] = __expf(e[j] - M); Z += e[j]; }
            #pragma unroll
            for (int o = 16; o; o >>= 1) Z += __shfl_xor_sync(~0u, Z, o);
            float rz = 1.f / Z;

            uint32_t* arow = g_attn + ((size_t)bp * SEQ + gq) * SEQ;
            if (v == 0) {
                #pragma unroll
                for (int j = 0; j < 12; j++)
                    arow[lane + 32 * j] = split_h2(e[j] * rz);
            } else {
                const int* mr = agent + ((size_t)head * SEQ + gq) * SEQ;
                #pragma unroll
                for (int j = 0; j < 12; j++) {
                    float a_same = unsplit_h2(arow[lane + 32 * j]);
                    float m = (float)mr[lane + 32 * j];
                    arow[lane + 32 * j] =
                        split_h2(m * a_same + (1.f - m) * e[j] * rz);
                }
            }
        }
    }
}

// ---------------------------------------------------------------------------
// AV on fp16x3 MMA (unchanged from R9).
// ---------------------------------------------------------------------------
#define AV_SMEM (13824 * 4)

__global__ void __launch_bounds__(256, 2)
av_mma_kernel()
{
    extern __shared__ uint32_t sm[];
    const uint32_t smb = (uint32_t)__cvta_generic_to_shared(sm);

    const int bp = blockIdx.y, m0 = blockIdx.x * 128;
    const int hh = bp >> 6, p = bp & 63;
    const int tid = threadIdx.x, lane = tid & 31, wid = tid >> 5;
    const int rbase = (wid & 3) * 32, cbase = (wid >> 2) * 32;
    const int lg = lane >> 2, lt = lane & 3;
    const int aRow = lane & 15, aCol = (lane >> 4) * 4;
    const int bRow = ((lane >> 4) & 1) * 8 + (lane & 7);
    const int bCol = ((lane >> 3) & 1) * 4;

    const uint32_t* A = g_attn + (size_t)bp * SS2 + (size_t)m0 * SEQ;
    const uint32_t* V = g_vT + (size_t)bp * HD * SEQ;

    float acc[2][4][4] = {};

    for (int ks = 0; ks < 6; ks++) {
        const int k0 = ks * 64;
        __syncthreads();
        #pragma unroll
        for (int i = 0; i < 16; i++) {
            int lin = i * 256 + tid;
            int row = lin >> 5, p2 = lin & 31;
            uint2 w = *(const uint2*)(A + (size_t)row * SEQ + k0 + p2 * 2);
            sm[row * 36 + p2]        = __byte_perm(w.x, w.y, 0x5410);
            sm[4608 + row * 36 + p2] = __byte_perm(w.x, w.y, 0x7632);
        }
        #pragma unroll
        for (int i = 0; i < 8; i++) {
            int lin = i * 256 + tid;
            int row = lin >> 5, p2 = lin & 31;
            uint2 w = *(const uint2*)(V + (size_t)row * SEQ + k0 + p2 * 2);
            sm[9216 + row * 36 + p2]  = __byte_perm(w.x, w.y, 0x5410);
            sm[11520 + row * 36 + p2] = __byte_perm(w.x, w.y, 0x7632);
        }
        __syncthreads();

        #pragma unroll
        for (int k16 = 0; k16 < 4; k16++) {
            const int ko = k16 * 8;
            uint32_t ah[2][4], al[2][4];
            #pragma unroll
            for (int mt = 0; mt < 2; mt++) {
                uint32_t aw = smb + ((rbase + mt * 16 + aRow) * 36 + aCol + ko) * 4;
                ldsm4(ah[mt][0], ah[mt][1], ah[mt][2], ah[mt][3], aw);
                ldsm4(al[mt][0], al[mt][1], al[mt][2], al[mt][3], aw + 18432);
            }
            #pragma unroll
            for (int pr = 0; pr < 2; pr++) {
                uint32_t bw = smb + 36864 + ((cbase + pr * 16 + bRow) * 36 + bCol + ko) * 4;
                uint32_t bh0, bh1, bh2, bh3, bl0, bl1, bl2, bl3;
                ldsm4(bh0, bh1, bh2, bh3, bw);
                ldsm4(bl0, bl1, bl2, bl3, bw + 9216);
                #pragma unroll
                for (int mt = 0; mt < 2; mt++) {
                    mma_f16(acc[mt][2 * pr],     ah[mt], bh0, bh1);
                    mma_f16(acc[mt][2 * pr],     ah[mt], bl0, bl1);
                    mma_f16(acc[mt][2 * pr],     al[mt], bh0, bh1);
                    mma_f16(acc[mt][2 * pr + 1], ah[mt], bh2, bh3);
                    mma_f16(acc[mt][2 * pr + 1], ah[mt], bl2, bl3);
                    mma_f16(acc[mt][2 * pr + 1], al[mt], bh2, bh3);
                }
            }
        }
    }

    #pragma unroll
    for (int mt = 0; mt < 2; mt++) {
        #pragma unroll
        for (int nt = 0; nt < 4; nt++) {
            #pragma unroll
            for (int cp = 0; cp < 4; cp++) {
                int q  = m0 + rbase + mt * 16 + lg + ((cp >= 2) ? 8 : 0);
                int dd = cbase + nt * 8 + lt * 2 + (cp & 1);
                g_c2_hl[((size_t)q * CIN + (dd * 8 + hh)) * 64 + p] =
                    split_h2(acc[mt][nt][cp]);
            }
        }
    }
}

// ---------------------------------------------------------------------------
extern "C" void kernel_launch(void* const* d_in, const int* in_sizes, int n_in,
                              void* d_out, int out_size)
{
    const float* inp       = (const float*)d_in[0];
    const float* attn_mask = (const float*)d_in[1];
    const int*   agent     = (const int*)  d_in[2];
    const float* w_in      = (const float*)d_in[3];
    const float* b_in      = (const float*)d_in[4];
    const float* w_out     = (const float*)d_in[5];
    const float* b_out     = (const float*)d_in[6];
    float*       out       = (float*)d_out;

    __half *wh_in, *wl_in, *wh_out, *wl_out;
    cudaGetSymbolAddress((void**)&wh_in,  g_wh_in);
    cudaGetSymbolAddress((void**)&wl_in,  g_wl_in);
    cudaGetSymbolAddress((void**)&wh_out, g_wh_out);
    cudaGetSymbolAddress((void**)&wl_out, g_wl_out);

    cudaFuncSetAttribute(conv_f16_kernel<2560, true>,
                         cudaFuncAttributeMaxDynamicSharedMemorySize, SMEM_BYTES);
    cudaFuncSetAttribute(conv_f16_kernel<512, false>,
                         cudaFuncAttributeMaxDynamicSharedMemorySize, SMEM_BYTES);
    cudaFuncSetAttribute(fused_qk_softmax_kernel,
                         cudaFuncAttributeMaxDynamicSharedMemorySize, FA_SMEM);
    cudaFuncSetAttribute(av_mma_kernel,
                         cudaFuncAttributeMaxDynamicSharedMemorySize, AV_SMEM);

    const int n_win  = 2560 * K9;
    const int n_wout = 512 * K9;
    split_w_kernel<<<(n_win + 255) / 256, 256>>>(w_in, wh_in, wl_in, n_win);
    split_w_kernel<<<(n_wout + 255) / 256, 256>>>(w_out, wh_out, wl_out, n_wout);

    // im2col expansion of raw input
    im2col_kernel<false><<<dim3(SEQ, 8), 256>>>(inp);

    // conv_in GEMM: M = 24576 (192 blocks of 128), N = 2560 (20 tiles)
    conv_f16_kernel<2560, true><<<dim3(20, 192), 256, SMEM_BYTES>>>(wh_in, wl_in, b_in, nullptr);

    // fused scores + dual softmax + agent blend -> packed attn
    fused_qk_softmax_kernel<<<dim3(6, BP), 256, FA_SMEM>>>(attn_mask, agent);

    // attn @ V on tensor cores -> packed conv2 input
    av_mma_kernel<<<dim3(3, BP), 256, AV_SMEM>>>();

    // im2col expansion of attention output (packed source)
    im2col_kernel<true><<<dim3(SEQ, 8), 256>>>(nullptr);

    // conv_out GEMM: N = 512 (4 tiles)
    conv_f16_kernel<512, false><<<dim3(4, 192), 256, SMEM_BYTES>>>(wh_out, wl_out, b_out, out);
}